// round 17
// baseline (speedup 1.0000x reference)
#include <cuda_runtime.h>
#include <cuda_bf16.h>
#include <cuda_fp16.h>
#include <cstdint>
#include <stdint.h>
#include <math.h>

#define NN 50000
#define EE 400000

// ---------------- scratch (device globals) ----------------
__device__ float g_y[(size_t)NN * 2048];     // q fp32 | s fp32 | k fp16 | v fp16 | l3 scratch
__device__ float g_h[(size_t)NN * 512];      // h fp16 lives here (as __half*)
__device__ int   g_rowptr[NN + 1];
__device__ int   g_cursor[NN];
__device__ int   g_perm[EE];
__device__ int   g_chunksum[256];

// ---------------- helpers ----------------
__device__ __forceinline__ uint32_t s2u(const void* p) {
    return (uint32_t)__cvta_generic_to_shared(p);
}
__device__ __forceinline__ void mma_bf16(float* c, const uint32_t* a, const uint32_t* b) {
    asm volatile(
        "mma.sync.aligned.m16n8k16.row.col.f32.bf16.bf16.f32 "
        "{%0,%1,%2,%3}, {%4,%5,%6,%7}, {%8,%9}, {%0,%1,%2,%3};"
        : "+f"(c[0]), "+f"(c[1]), "+f"(c[2]), "+f"(c[3])
        : "r"(a[0]), "r"(a[1]), "r"(a[2]), "r"(a[3]), "r"(b[0]), "r"(b[1]));
}
__device__ __forceinline__ void ldsm4(uint32_t addr, uint32_t& r0, uint32_t& r1,
                                      uint32_t& r2, uint32_t& r3) {
    asm volatile("ldmatrix.sync.aligned.m8n8.x4.shared.b16 {%0,%1,%2,%3}, [%4];"
                 : "=r"(r0), "=r"(r1), "=r"(r2), "=r"(r3) : "r"(addr));
}
__device__ __forceinline__ void ldsm4t(uint32_t addr, uint32_t& r0, uint32_t& r1,
                                       uint32_t& r2, uint32_t& r3) {
    asm volatile("ldmatrix.sync.aligned.m8n8.x4.trans.shared.b16 {%0,%1,%2,%3}, [%4];"
                 : "=r"(r0), "=r"(r1), "=r"(r2), "=r"(r3) : "r"(addr));
}
__device__ __forceinline__ void split2(float x, float y, uint32_t& hi, uint32_t& lo) {
    __nv_bfloat16 hx = __float2bfloat16_rn(x);
    __nv_bfloat16 hy = __float2bfloat16_rn(y);
    __nv_bfloat162 hh; hh.x = hx; hh.y = hy;
    hi = *(uint32_t*)&hh;
    __nv_bfloat162 ll;
    ll.x = __float2bfloat16_rn(x - __bfloat162float(hx));
    ll.y = __float2bfloat16_rn(y - __bfloat162float(hy));
    lo = *(uint32_t*)&ll;
}
__device__ __forceinline__ void unpack8(uint4 u, float* f) {
    float2 a = __half22float2(*(__half2*)&u.x);
    float2 b = __half22float2(*(__half2*)&u.y);
    float2 c = __half22float2(*(__half2*)&u.z);
    float2 d = __half22float2(*(__half2*)&u.w);
    f[0] = a.x; f[1] = a.y; f[2] = b.x; f[3] = b.y;
    f[4] = c.x; f[5] = c.y; f[6] = d.x; f[7] = d.y;
}

// ---------------- CSR build (by dst) ----------------
__global__ void k_zero_rowptr(int n) {
    int i = blockIdx.x * blockDim.x + threadIdx.x;
    if (i < n) g_rowptr[i] = 0;
}
__global__ void k_count(const int* __restrict__ dst, int E) {
    int e = blockIdx.x * blockDim.x + threadIdx.x;
    if (e < E) atomicAdd(&g_rowptr[dst[e] + 1], 1);
}
__global__ void k_block_sums(int n) {
    __shared__ int sh[256];
    int i = blockIdx.x * 256 + threadIdx.x;
    sh[threadIdx.x] = (i < n) ? g_rowptr[i] : 0;
    __syncthreads();
    for (int o = 128; o > 0; o >>= 1) {
        if (threadIdx.x < o) sh[threadIdx.x] += sh[threadIdx.x + o];
        __syncthreads();
    }
    if (threadIdx.x == 0) g_chunksum[blockIdx.x] = sh[0];
}
__global__ void k_scan_chunks(int nch) {
    if (threadIdx.x == 0 && blockIdx.x == 0) {
        int running = 0;
        for (int i = 0; i < nch; i++) {
            int t = g_chunksum[i];
            g_chunksum[i] = running;
            running += t;
        }
    }
}
__global__ void k_block_scan(int n) {
    __shared__ int sh[256];
    int i = blockIdx.x * 256 + threadIdx.x;
    int t = threadIdx.x;
    sh[t] = (i < n) ? g_rowptr[i] : 0;
    __syncthreads();
    for (int o = 1; o < 256; o <<= 1) {
        int v = sh[t];
        int u = (t >= o) ? sh[t - o] : 0;
        __syncthreads();
        sh[t] = v + u;
        __syncthreads();
    }
    if (i < n) g_rowptr[i] = sh[t] + g_chunksum[blockIdx.x];
}
__global__ void k_cursor(int n) {
    int i = blockIdx.x * blockDim.x + threadIdx.x;
    if (i < n) g_cursor[i] = g_rowptr[i];
}
__global__ void k_scatter(const int* __restrict__ dst, int E) {
    int e = blockIdx.x * blockDim.x + threadIdx.x;
    if (e < E) {
        int p = atomicAdd(&g_cursor[dst[e]], 1);
        g_perm[p] = e;
    }
}

// ---------------- BF16x3 tensor-core GEMM; fp32 or fp16 A; k/v outputs fp16 ----------------
#define A_STR 40
#define B_STR 136

template <bool AHALF>
__global__ void __launch_bounds__(256) k_mma4(const void* __restrict__ AgV,
                                              const float* __restrict__ W0, const float* __restrict__ b0, float* __restrict__ o0,
                                              const float* __restrict__ W1, const float* __restrict__ b1, float* __restrict__ o1,
                                              const float* __restrict__ W2, const float* __restrict__ b2, float* __restrict__ o2,
                                              const float* __restrict__ W3, const float* __restrict__ b3, float* __restrict__ o3,
                                              int M, int K, int F) {
    __shared__ __align__(16) __nv_bfloat16 As_hi[128 * A_STR];
    __shared__ __align__(16) __nv_bfloat16 As_lo[128 * A_STR];
    __shared__ __align__(16) __nv_bfloat16 Bs_hi[32 * B_STR];
    __shared__ __align__(16) __nv_bfloat16 Bs_lo[32 * B_STR];

    int tid = threadIdx.x;
    int warp = tid >> 5, lane = tid & 31;
    int wm = warp >> 2;
    int wn = warp & 3;
    int gid = lane >> 2;
    int l4 = lane & 3;

    int nb = F / 128;
    int bsel = blockIdx.x / nb;
    int bn = blockIdx.x % nb;
    int bm = blockIdx.y;
    const float* W = bsel == 0 ? W0 : bsel == 1 ? W1 : bsel == 2 ? W2 : W3;
    const float* bias = bsel == 0 ? b0 : bsel == 1 ? b1 : bsel == 2 ? b2 : b3;
    float* outp = bsel == 0 ? o0 : bsel == 1 ? o1 : bsel == 2 ? o2 : o3;
    bool fp16out = (bsel == 1) || (bsel == 2);

    uint32_t* Ah32 = (uint32_t*)As_hi;
    uint32_t* Al32 = (uint32_t*)As_lo;
    uint32_t* Bh32 = (uint32_t*)Bs_hi;
    uint32_t* Bl32 = (uint32_t*)Bs_lo;
    uint32_t sAh = s2u(As_hi), sAl = s2u(As_lo);
    uint32_t sBh = s2u(Bs_hi), sBl = s2u(Bs_lo);

    int q = lane >> 3, r8 = lane & 7;
    int a_row_off = (q & 1) * 8 + r8;
    int a_col_off = (q >> 1) * 8;
    int b_k_off = (q & 1) * 8 + r8;
    int b_nblk = q >> 1;

    float acc[4][4][4];
#pragma unroll
    for (int i = 0; i < 4; i++)
#pragma unroll
        for (int j = 0; j < 4; j++)
#pragma unroll
            for (int r = 0; r < 4; r++) acc[i][j][r] = 0.f;

    for (int k0 = 0; k0 < K; k0 += 32) {
        __syncthreads();
#pragma unroll
        for (int i = 0; i < 4; i++) {
            int r = (tid >> 3) + i * 32;
            int fc = (tid & 7) * 4;
            int gr = bm * 128 + r;
            float4 v = make_float4(0.f, 0.f, 0.f, 0.f);
            if (gr < M) {
                if constexpr (AHALF) {
                    const __half* A = (const __half*)AgV;
                    uint2 u = *(const uint2*)(A + (size_t)gr * K + k0 + fc);
                    float2 p0 = __half22float2(*(__half2*)&u.x);
                    float2 p1 = __half22float2(*(__half2*)&u.y);
                    v = make_float4(p0.x, p0.y, p1.x, p1.y);
                } else {
                    const float* A = (const float*)AgV;
                    v = *(const float4*)(A + (size_t)gr * K + k0 + fc);
                }
            }
            uint32_t h0, l0, h1, l1;
            split2(v.x, v.y, h0, l0);
            split2(v.z, v.w, h1, l1);
            int base = r * (A_STR / 2) + fc / 2;
            Ah32[base] = h0; Ah32[base + 1] = h1;
            Al32[base] = l0; Al32[base + 1] = l1;
        }
        {
            int kk = tid >> 3;
            const float* Wrow = W + (size_t)(k0 + kk) * F + bn * 128;
#pragma unroll
            for (int i = 0; i < 4; i++) {
                int n = (tid & 7) * 4 + i * 32;
                float4 v = *(const float4*)(Wrow + n);
                uint32_t h0, l0, h1, l1;
                split2(v.x, v.y, h0, l0);
                split2(v.z, v.w, h1, l1);
                int base = kk * (B_STR / 2) + n / 2;
                Bh32[base] = h0; Bh32[base + 1] = h1;
                Bl32[base] = l0; Bl32[base + 1] = l1;
            }
        }
        __syncthreads();

#pragma unroll
        for (int ks = 0; ks < 32; ks += 16) {
            uint32_t ah[4][4], al[4][4], bh[4][2], bl[4][2];
#pragma unroll
            for (int tm = 0; tm < 4; tm++) {
                int mbase = wm * 64 + tm * 16;
                uint32_t off = (uint32_t)((mbase + a_row_off) * (A_STR * 2) +
                                          (ks + a_col_off) * 2);
                ldsm4(sAh + off, ah[tm][0], ah[tm][1], ah[tm][2], ah[tm][3]);
                ldsm4(sAl + off, al[tm][0], al[tm][1], al[tm][2], al[tm][3]);
            }
#pragma unroll
            for (int tnp = 0; tnp < 2; tnp++) {
                int n0 = wn * 32 + (tnp * 2 + b_nblk) * 8;
                uint32_t off = (uint32_t)((ks + b_k_off) * (B_STR * 2) + n0 * 2);
                ldsm4t(sBh + off, bh[2 * tnp][0], bh[2 * tnp][1],
                       bh[2 * tnp + 1][0], bh[2 * tnp + 1][1]);
                ldsm4t(sBl + off, bl[2 * tnp][0], bl[2 * tnp][1],
                       bl[2 * tnp + 1][0], bl[2 * tnp + 1][1]);
            }
#pragma unroll
            for (int tm = 0; tm < 4; tm++)
#pragma unroll
                for (int tn = 0; tn < 4; tn++) {
                    mma_bf16(acc[tm][tn], ah[tm], bh[tn]);
                    mma_bf16(acc[tm][tn], ah[tm], bl[tn]);
                    mma_bf16(acc[tm][tn], al[tm], bh[tn]);
                }
        }
    }

#pragma unroll
    for (int tm = 0; tm < 4; tm++) {
        int r0 = bm * 128 + wm * 64 + tm * 16 + gid;
        int r1 = r0 + 8;
#pragma unroll
        for (int tn = 0; tn < 4; tn++) {
            int c = bn * 128 + wn * 32 + tn * 8 + l4 * 2;
            float v00 = acc[tm][tn][0] + bias[c];
            float v01 = acc[tm][tn][1] + bias[c + 1];
            float v10 = acc[tm][tn][2] + bias[c];
            float v11 = acc[tm][tn][3] + bias[c + 1];
            if (fp16out) {
                __half* op = (__half*)outp;
                if (r0 < M) *(__half2*)(op + (size_t)r0 * F + c) = __floats2half2_rn(v00, v01);
                if (r1 < M) *(__half2*)(op + (size_t)r1 * F + c) = __floats2half2_rn(v10, v11);
            } else {
                if (r0 < M) {
                    outp[(size_t)r0 * F + c] = v00;
                    outp[(size_t)r0 * F + c + 1] = v01;
                }
                if (r1 < M) {
                    outp[(size_t)r1 * F + c] = v10;
                    outp[(size_t)r1 * F + c + 1] = v11;
                }
            }
        }
    }
}

// ---------------- FUSED edge phase (2x unroll, fp16 k/v); PROJ fuses layer-3 projection ----
template <int H, int C, bool PROJ>
__global__ void k_edge(const int* __restrict__ src,
                       const float* __restrict__ q, const __half* __restrict__ kk,
                       const __half* __restrict__ vv, const float* __restrict__ sskip,
                       const float* __restrict__ lng, const float* __restrict__ lnb,
                       __half* __restrict__ hout,
                       const float* __restrict__ Wq3, const float* __restrict__ bq3,
                       const float* __restrict__ Wk3, const float* __restrict__ bk3,
                       const float* __restrict__ Wv3, const float* __restrict__ bv3,
                       const float* __restrict__ Ws3, const float* __restrict__ bs3,
                       float* __restrict__ q3, float* __restrict__ k3,
                       float* __restrict__ v3, float* __restrict__ s3,
                       int n, float scale) {
    constexpr int F = H * C, TC = F / 256;
    int node = (blockIdx.x * blockDim.x + threadIdx.x) >> 5;
    int lane = threadIdx.x & 31;
    if (node >= n) return;
    int s0 = g_rowptr[node], s1 = g_rowptr[node + 1];

    float qf[TC][8];
    const float4* qp = (const float4*)(q + (size_t)node * F);
#pragma unroll
    for (int t = 0; t < TC; t++) {
        int j = lane + 32 * t;
        float4 a = qp[2 * j], b = qp[2 * j + 1];
        qf[t][0] = a.x; qf[t][1] = a.y; qf[t][2] = a.z; qf[t][3] = a.w;
        qf[t][4] = b.x; qf[t][5] = b.y; qf[t][6] = b.z; qf[t][7] = b.w;
    }

    float m[H], den[H];
#pragma unroll
    for (int h = 0; h < H; h++) { m[h] = -INFINITY; den[h] = 0.f; }
    float acc[TC][8];
#pragma unroll
    for (int t = 0; t < TC; t++)
#pragma unroll
        for (int i = 0; i < 8; i++) acc[t][i] = 0.f;

    auto dotChunk = [&](const float* kf, int t, float* d) {
        float dd = qf[t][0] * kf[0] + qf[t][1] * kf[1] + qf[t][2] * kf[2] + qf[t][3] * kf[3]
                 + qf[t][4] * kf[4] + qf[t][5] * kf[5] + qf[t][6] * kf[6] + qf[t][7] * kf[7];
        if constexpr (C == 128) {
            if (lane < 16) d[2 * t] += dd;
            else d[2 * t + 1] += dd;
        } else {
            int h = lane >> 3;
            d[0] += (h == 0) ? dd : 0.f;
            d[1] += (h == 1) ? dd : 0.f;
            d[2] += (h == 2) ? dd : 0.f;
            d[3] += (h == 3) ? dd : 0.f;
        }
    };
    auto update = [&](const float (*vr)[8], const float* d) {
        float fa[H], w[H];
#pragma unroll
        for (int h = 0; h < H; h++) {
            float nm = fmaxf(m[h], d[h]);
            fa[h] = __expf(m[h] - nm);
            w[h] = __expf(d[h] - nm);
            den[h] = den[h] * fa[h] + w[h];
            m[h] = nm;
        }
#pragma unroll
        for (int t = 0; t < TC; t++) {
            float f, ww;
            if constexpr (C == 128) {
                f = (lane < 16) ? fa[2 * t] : fa[2 * t + 1];
                ww = (lane < 16) ? w[2 * t] : w[2 * t + 1];
            } else {
                f = (lane < 8) ? fa[0] : (lane < 16) ? fa[1] : (lane < 24) ? fa[2] : fa[3];
                ww = (lane < 8) ? w[0] : (lane < 16) ? w[1] : (lane < 24) ? w[2] : w[3];
            }
#pragma unroll
            for (int i = 0; i < 8; i++)
                acc[t][i] = fmaf(ww, vr[t][i], acc[t][i] * f);
        }
    };

    int j = s0;
    for (; j + 1 < s1; j += 2) {
        int e0 = g_perm[j], e1 = g_perm[j + 1];
        int sv0 = src[e0], sv1 = src[e1];
        const uint4* kp0 = (const uint4*)(kk + (size_t)sv0 * F);
        const uint4* vp0 = (const uint4*)(vv + (size_t)sv0 * F);
        const uint4* kp1 = (const uint4*)(kk + (size_t)sv1 * F);
        const uint4* vp1 = (const uint4*)(vv + (size_t)sv1 * F);

        uint4 kc0[TC], vc0[TC], kc1[TC], vc1[TC];
#pragma unroll
        for (int t = 0; t < TC; t++) {
            int jj = lane + 32 * t;
            kc0[t] = kp0[jj]; vc0[t] = vp0[jj];
            kc1[t] = kp1[jj]; vc1[t] = vp1[jj];
        }

        float d0[H], d1[H];
#pragma unroll
        for (int h = 0; h < H; h++) { d0[h] = 0.f; d1[h] = 0.f; }
        float vr0[TC][8], vr1[TC][8];
#pragma unroll
        for (int t = 0; t < TC; t++) {
            float kf[8];
            unpack8(kc0[t], kf);
            unpack8(vc0[t], vr0[t]);
            dotChunk(kf, t, d0);
            unpack8(kc1[t], kf);
            unpack8(vc1[t], vr1[t]);
            dotChunk(kf, t, d1);
        }
#pragma unroll
        for (int o = 16; o; o >>= 1) {
#pragma unroll
            for (int h = 0; h < H; h++) {
                d0[h] += __shfl_xor_sync(0xffffffffu, d0[h], o);
                d1[h] += __shfl_xor_sync(0xffffffffu, d1[h], o);
            }
        }
#pragma unroll
        for (int h = 0; h < H; h++) { d0[h] *= scale; d1[h] *= scale; }

        update(vr0, d0);
        update(vr1, d1);
    }
    if (j < s1) {
        int e = g_perm[j];
        int sv = src[e];
        const uint4* kp = (const uint4*)(kk + (size_t)sv * F);
        const uint4* vp = (const uint4*)(vv + (size_t)sv * F);
        float d[H];
#pragma unroll
        for (int h = 0; h < H; h++) d[h] = 0.f;
        float vr[TC][8];
#pragma unroll
        for (int t = 0; t < TC; t++) {
            int jj = lane + 32 * t;
            float kf[8];
            unpack8(kp[jj], kf);
            unpack8(vp[jj], vr[t]);
            dotChunk(kf, t, d);
        }
#pragma unroll
        for (int h = 0; h < H; h++) {
#pragma unroll
            for (int o = 16; o; o >>= 1) d[h] += __shfl_xor_sync(0xffffffffu, d[h], o);
            d[h] *= scale;
        }
        update(vr, d);
    }

    // normalize
    float inv[H];
#pragma unroll
    for (int h = 0; h < H; h++) inv[h] = 1.f / (den[h] + 1e-16f);
#pragma unroll
    for (int t = 0; t < TC; t++) {
        float f;
        if constexpr (C == 128) f = (lane < 16) ? inv[2 * t] : inv[2 * t + 1];
        else f = (lane < 8) ? inv[0] : (lane < 16) ? inv[1] : (lane < 24) ? inv[2] : inv[3];
#pragma unroll
        for (int i = 0; i < 8; i++) acc[t][i] *= f;
    }

    // skip
    const float4* sp = (const float4*)(sskip + (size_t)node * F);
#pragma unroll
    for (int t = 0; t < TC; t++) {
        int jj = lane + 32 * t;
        float4 a = sp[2 * jj], b = sp[2 * jj + 1];
        acc[t][0] += a.x; acc[t][1] += a.y; acc[t][2] += a.z; acc[t][3] += a.w;
        acc[t][4] += b.x; acc[t][5] += b.y; acc[t][6] += b.z; acc[t][7] += b.w;
    }

    // LayerNorm
    float s = 0.f;
#pragma unroll
    for (int t = 0; t < TC; t++)
#pragma unroll
        for (int i = 0; i < 8; i++) s += acc[t][i];
#pragma unroll
    for (int o = 16; o; o >>= 1) s += __shfl_xor_sync(0xffffffffu, s, o);
    float mean = s / (float)F;
    float vs = 0.f;
#pragma unroll
    for (int t = 0; t < TC; t++)
#pragma unroll
        for (int i = 0; i < 8; i++) {
            float dx = acc[t][i] - mean;
            vs = fmaf(dx, dx, vs);
        }
#pragma unroll
    for (int o = 16; o; o >>= 1) vs += __shfl_xor_sync(0xffffffffu, vs, o);
    float r = rsqrtf(vs / (float)F + 1e-5f);
    const float4* gp = (const float4*)lng;
    const float4* bp = (const float4*)lnb;

    if constexpr (PROJ) {
        // layer-3 fused projection: TC == 1; lane owns channels 8*lane..8*lane+7
        float ov[8];
        {
            int jj = lane;
            float4 g0 = gp[2 * jj], b0 = bp[2 * jj];
            float4 g1 = gp[2 * jj + 1], b1 = bp[2 * jj + 1];
            float t0 = (acc[0][0] - mean) * r * g0.x + b0.x;
            float t1 = (acc[0][1] - mean) * r * g0.y + b0.y;
            float t2 = (acc[0][2] - mean) * r * g0.z + b0.z;
            float t3 = (acc[0][3] - mean) * r * g0.w + b0.w;
            float t4 = (acc[0][4] - mean) * r * g1.x + b1.x;
            float t5 = (acc[0][5] - mean) * r * g1.y + b1.y;
            float t6 = (acc[0][6] - mean) * r * g1.z + b1.z;
            float t7 = (acc[0][7] - mean) * r * g1.w + b1.w;
            ov[0] = t0 > 0.f ? t0 : expm1f(t0);
            ov[1] = t1 > 0.f ? t1 : expm1f(t1);
            ov[2] = t2 > 0.f ? t2 : expm1f(t2);
            ov[3] = t3 > 0.f ? t3 : expm1f(t3);
            ov[4] = t4 > 0.f ? t4 : expm1f(t4);
            ov[5] = t5 > 0.f ? t5 : expm1f(t5);
            ov[6] = t6 > 0.f ? t6 : expm1f(t6);
            ov[7] = t7 > 0.f ? t7 : expm1f(t7);
        }
        float a[8];
#pragma unroll
        for (int i = 0; i < 8; i++) a[i] = 0.f;
#pragma unroll
        for (int i = 0; i < 8; i++) {
            int ch = 8 * lane + i;
            float2 wq = ((const float2*)Wq3)[ch];
            float2 wk = ((const float2*)Wk3)[ch];
            float2 wv = ((const float2*)Wv3)[ch];
            float2 ws = ((const float2*)Ws3)[ch];
            a[0] = fmaf(ov[i], wq.x, a[0]);
            a[1] = fmaf(ov[i], wq.y, a[1]);
            a[2] = fmaf(ov[i], wk.x, a[2]);
            a[3] = fmaf(ov[i], wk.y, a[3]);
            a[4] = fmaf(ov[i], wv.x, a[4]);
            a[5] = fmaf(ov[i], wv.y, a[5]);
            a[6] = fmaf(ov[i], ws.x, a[6]);
            a[7] = fmaf(ov[i], ws.y, a[7]);
        }
#pragma unroll
        for (int o = 16; o; o >>= 1)
#pragma unroll
            for (int i = 0; i < 8; i++) a[i] += __shfl_xor_sync(0xffffffffu, a[i], o);
        if (lane == 0) {
            q3[(size_t)node * 2 + 0] = a[0] + bq3[0];
            q3[(size_t)node * 2 + 1] = a[1] + bq3[1];
            k3[(size_t)node * 2 + 0] = a[2] + bk3[0];
            k3[(size_t)node * 2 + 1] = a[3] + bk3[1];
            v3[(size_t)node * 2 + 0] = a[4] + bv3[0];
            v3[(size_t)node * 2 + 1] = a[5] + bv3[1];
            s3[(size_t)node * 2 + 0] = a[6] + bs3[0];
            s3[(size_t)node * 2 + 1] = a[7] + bs3[1];
        }
    } else {
        // write h as fp16 (8 halves per lane chunk)
        uint4* op = (uint4*)(hout + (size_t)node * F);
#pragma unroll
        for (int t = 0; t < TC; t++) {
            int jj = lane + 32 * t;
            float4 g0 = gp[2 * jj], b0 = bp[2 * jj];
            float4 g1 = gp[2 * jj + 1], b1 = bp[2 * jj + 1];
            float t0 = (acc[t][0] - mean) * r * g0.x + b0.x;
            float t1 = (acc[t][1] - mean) * r * g0.y + b0.y;
            float t2 = (acc[t][2] - mean) * r * g0.z + b0.z;
            float t3 = (acc[t][3] - mean) * r * g0.w + b0.w;
            float t4 = (acc[t][4] - mean) * r * g1.x + b1.x;
            float t5 = (acc[t][5] - mean) * r * g1.y + b1.y;
            float t6 = (acc[t][6] - mean) * r * g1.z + b1.z;
            float t7 = (acc[t][7] - mean) * r * g1.w + b1.w;
            t0 = t0 > 0.f ? t0 : expm1f(t0);
            t1 = t1 > 0.f ? t1 : expm1f(t1);
            t2 = t2 > 0.f ? t2 : expm1f(t2);
            t3 = t3 > 0.f ? t3 : expm1f(t3);
            t4 = t4 > 0.f ? t4 : expm1f(t4);
            t5 = t5 > 0.f ? t5 : expm1f(t5);
            t6 = t6 > 0.f ? t6 : expm1f(t6);
            t7 = t7 > 0.f ? t7 : expm1f(t7);
            uint4 u;
            *(__half2*)&u.x = __floats2half2_rn(t0, t1);
            *(__half2*)&u.y = __floats2half2_rn(t2, t3);
            *(__half2*)&u.z = __floats2half2_rn(t4, t5);
            *(__half2*)&u.w = __floats2half2_rn(t6, t7);
            op[jj] = u;
        }
    }
}

// ---------------- layer 3 fused finalize ----------------
__global__ void k_final3(const int* __restrict__ src,
                         const float* __restrict__ q2, const float* __restrict__ k2,
                         const float* __restrict__ v2, const float* __restrict__ s3,
                         float* __restrict__ out, int n, float scale) {
    int i = blockIdx.x * blockDim.x + threadIdx.x;
    if (i >= n) return;
    int s0 = g_rowptr[i], s1 = g_rowptr[i + 1];
    float q0 = q2[(size_t)i * 2 + 0], q1 = q2[(size_t)i * 2 + 1];
    float m = -INFINITY, den = 0.f, a0 = 0.f, a1 = 0.f;
    for (int j = s0; j < s1; j++) {
        int e = g_perm[j];
        int sv = src[e];
        float sc = (q0 * k2[(size_t)sv * 2] + q1 * k2[(size_t)sv * 2 + 1]) * scale;
        float nm = fmaxf(m, sc);
        float fa = __expf(m - nm);
        float w = __expf(sc - nm);
        den = den * fa + w;
        a0 = fmaf(w, v2[(size_t)sv * 2 + 0], a0 * fa);
        a1 = fmaf(w, v2[(size_t)sv * 2 + 1], a1 * fa);
        m = nm;
    }
    float inv = 1.f / (den + 1e-16f);
    a0 *= inv; a1 *= inv;
    float h0 = a0 + s3[(size_t)i * 2 + 0];
    float h1 = a1 + s3[(size_t)i * 2 + 1];
    float mx = fmaxf(h0, h1);
    float lse = mx + logf(expf(h0 - mx) + expf(h1 - mx));
    out[2 * i + 0] = h0 - lse;
    out[2 * i + 1] = h1 - lse;
}

// ---------------- launch ----------------
static inline int cdiv(int a, int b) { return (a + b - 1) / b; }

extern "C" void kernel_launch(void* const* d_in, const int* in_sizes, int n_in,
                              void* d_out, int out_size) {
    const float* x = (const float*)d_in[0];
    const int* ei = (const int*)d_in[1];
    const int N = in_sizes[0] / 128;
    const int E = in_sizes[1] / 2;
    const int* src = ei;
    const int* dst = ei + E;

    const float *Wq1 = (const float*)d_in[2],  *bq1 = (const float*)d_in[3];
    const float *Wk1 = (const float*)d_in[4],  *bk1 = (const float*)d_in[5];
    const float *Wv1 = (const float*)d_in[6],  *bv1 = (const float*)d_in[7];
    const float *Ws1 = (const float*)d_in[8],  *bs1 = (const float*)d_in[9];
    const float *Wq2 = (const float*)d_in[10], *bq2 = (const float*)d_in[11];
    const float *Wk2 = (const float*)d_in[12], *bk2 = (const float*)d_in[13];
    const float *Wv2 = (const float*)d_in[14], *bv2 = (const float*)d_in[15];
    const float *Ws2 = (const float*)d_in[16], *bs2 = (const float*)d_in[17];
    const float *Wq3 = (const float*)d_in[18], *bq3 = (const float*)d_in[19];
    const float *Wk3 = (const float*)d_in[20], *bk3 = (const float*)d_in[21];
    const float *Wv3 = (const float*)d_in[22], *bv3 = (const float*)d_in[23];
    const float *Ws3 = (const float*)d_in[24], *bs3 = (const float*)d_in[25];
    const float *ln1g = (const float*)d_in[26], *ln1b = (const float*)d_in[27];
    const float *ln2g = (const float*)d_in[28], *ln2b = (const float*)d_in[29];
    float* out = (float*)d_out;

    static float *yb = nullptr, *hb = nullptr;
    static bool cfg = false;
    static cudaStream_t s2;
    static cudaEvent_t evFork, evJoin;
    if (!cfg) {
        void* p;
        cudaGetSymbolAddress(&p, g_y); yb = (float*)p;
        cudaGetSymbolAddress(&p, g_h); hb = (float*)p;
        cudaStreamCreateWithFlags(&s2, cudaStreamNonBlocking);
        cudaEventCreateWithFlags(&evFork, cudaEventDisableTiming);
        cudaEventCreateWithFlags(&evJoin, cudaEventDisableTiming);
        cfg = true;
    }

    float* q = yb;
    float* sOut = yb + (size_t)NN * 512;
    __half* kh = (__half*)(yb + (size_t)NN * 1024);
    __half* vh = (__half*)(yb + (size_t)NN * 1280);
    float* q3 = yb + (size_t)NN * 1536;
    float* k3 = q3 + (size_t)NN * 2;
    float* v3 = k3 + (size_t)NN * 2;
    float* s3 = v3 + (size_t)NN * 2;
    __half* hh = (__half*)hb;

    const int TB = 256;

    // ---- fork: CSR build on s2, overlapped with layer-1 GEMM ----
    cudaEventRecord(evFork, 0);
    cudaStreamWaitEvent(s2, evFork, 0);

    int n1 = N + 1;
    int nch = cdiv(n1, 256);
    k_zero_rowptr<<<cdiv(n1, TB), TB, 0, s2>>>(n1);
    k_count<<<cdiv(E, TB), TB, 0, s2>>>(dst, E);
    k_block_sums<<<nch, 256, 0, s2>>>(n1);
    k_scan_chunks<<<1, 32, 0, s2>>>(nch);
    k_block_scan<<<nch, 256, 0, s2>>>(n1);
    k_cursor<<<cdiv(N, TB), TB, 0, s2>>>(N);
    k_scatter<<<cdiv(E, TB), TB, 0, s2>>>(dst, E);
    cudaEventRecord(evJoin, s2);

    // ================= layer 1: K=128, F=512, H=4, C=128 =================
    {
        int K = 128, F = 512;
        dim3 grid(4 * F / 128, cdiv(N, 128));
        k_mma4<false><<<grid, 256>>>(x, Wq1, bq1, q, Wk1, bk1, (float*)kh, Wv1, bv1, (float*)vh,
                                     Ws1, bs1, sOut, N, K, F);
        cudaStreamWaitEvent(0, evJoin, 0);
        k_edge<4, 128, false><<<cdiv(N * 32, TB), TB>>>(
            src, q, kh, vh, sOut, ln1g, ln1b, hh,
            nullptr, nullptr, nullptr, nullptr, nullptr, nullptr, nullptr, nullptr,
            nullptr, nullptr, nullptr, nullptr, N, 0.08838834764831845f);
    }
    // ================= layer 2 + fused layer-3 projection =================
    {
        int K = 512, F = 256;
        dim3 grid(4 * F / 128, cdiv(N, 128));
        k_mma4<true><<<grid, 256>>>(hh, Wq2, bq2, q, Wk2, bk2, (float*)kh, Wv2, bv2, (float*)vh,
                                    Ws2, bs2, sOut, N, K, F);
        k_edge<4, 64, true><<<cdiv(N * 32, TB), TB>>>(
            src, q, kh, vh, sOut, ln2g, ln2b, nullptr,
            Wq3, bq3, Wk3, bk3, Wv3, bv3, Ws3, bs3,
            q3, k3, v3, s3, N, 0.125f);
    }
    // ================= layer 3 finalize =================
    k_final3<<<cdiv(N, TB), TB>>>(src, q3, k3, v3, s3, out, N, 0.7071067811865475f);
}